// round 8
// baseline (speedup 1.0000x reference)
#include <cuda_runtime.h>
#include <cuda_fp16.h>
#include <cuda_bf16.h>
#include <stdint.h>

// Problem constants
#define NB   4        // batches
#define NQ   2048     // N_LC = N_TE
#define NP   2049     // NQ + dustbin
#define MD   256      // feature dim D
#define STR  2064     // padded row stride (elements) for K matrices / vectors

// Persistent sink config: 148 blocks, 37/batch, 56 rows/block
#define NBLK 148
#define SUBB 37
#define RPB  56

// ---------------- device scratch (static, no allocation) ----------------
static __device__ __half g_Kh[(size_t)NB * NP * STR];   // exp(Z), row-major, fp16
static __device__ __half g_KT[(size_t)NB * NP * STR];   // exp(Z)^T, fp16
static __device__ float  g_f1[(size_t)NB * NQ * MD];    // MLP(lc) output
static __device__ float  g_f2[(size_t)NB * NQ * MD];    // MLP(te) output
static __device__ float  g_h1[(size_t)NB * NQ * MD];    // hidden lc
static __device__ float  g_h2[(size_t)NB * NQ * MD];    // hidden te
static __device__ __nv_bfloat16 g_s1h[(size_t)NB * NQ * MD];  // f1 split hi
static __device__ __nv_bfloat16 g_s1l[(size_t)NB * NQ * MD];  // f1 split lo
static __device__ __nv_bfloat16 g_s2h[(size_t)NB * NQ * MD];  // f2 split hi
static __device__ __nv_bfloat16 g_s2l[(size_t)NB * NQ * MD];  // f2 split lo
static __device__ float  g_a [NB * STR];                // scaling vec a
static __device__ float  g_bv[NB * STR];                // scaling vec b
static __device__ volatile int g_flag[NB][64];          // per-batch barrier flags

// ---------------- MLP GEMM: 2 pointer sets selected by blockIdx.z ----------
struct MlpArgs {
    const float* A[2];
    const float* B[2];
    const float* bias[2];
    float* C[2];
};

__global__ __launch_bounds__(256, 2)
void sgemm_mlp(MlpArgs args, int relu)
{
    __shared__ float As[8][128];
    __shared__ float Bs[8][128];
    const int z = blockIdx.z;
    const float* A = args.A[z];
    const float* B = args.B[z];
    const float* bias = args.bias[z];
    float* C = args.C[z];
    const int K = MD;

    const int tid = threadIdx.x;
    const int tx = tid & 15, ty = tid >> 4;
    const int brow = blockIdx.y << 7;
    const int bcol = blockIdx.x << 7;
    const int lr = tid >> 1;
    const int lk = (tid & 1) << 2;

    const float* Ald = A + (long long)(brow + lr) * K + lk;
    const float* Bld = B + (long long)(bcol + lr) * K + lk;

    float acc[8][8];
#pragma unroll
    for (int i = 0; i < 8; i++)
#pragma unroll
        for (int j = 0; j < 8; j++) acc[i][j] = 0.f;

    for (int kk = 0; kk < K; kk += 8) {
        float4 av = *(const float4*)(Ald + kk);
        float4 bv = *(const float4*)(Bld + kk);
        __syncthreads();
        As[lk + 0][lr] = av.x; As[lk + 1][lr] = av.y;
        As[lk + 2][lr] = av.z; As[lk + 3][lr] = av.w;
        Bs[lk + 0][lr] = bv.x; Bs[lk + 1][lr] = bv.y;
        Bs[lk + 2][lr] = bv.z; Bs[lk + 3][lr] = bv.w;
        __syncthreads();
#pragma unroll
        for (int k = 0; k < 8; k++) {
            float ar[8], br[8];
            *(float4*)&ar[0] = *(const float4*)&As[k][ty * 4];
            *(float4*)&ar[4] = *(const float4*)&As[k][ty * 4 + 64];
            *(float4*)&br[0] = *(const float4*)&Bs[k][tx * 4];
            *(float4*)&br[4] = *(const float4*)&Bs[k][tx * 4 + 64];
#pragma unroll
            for (int i = 0; i < 8; i++)
#pragma unroll
                for (int j = 0; j < 8; j++)
                    acc[i][j] = fmaf(ar[i], br[j], acc[i][j]);
        }
    }

#pragma unroll
    for (int i = 0; i < 8; i++) {
        int row = brow + ty * 4 + ((i < 4) ? i : 60 + i);
#pragma unroll
        for (int j = 0; j < 8; j++) {
            int col = bcol + tx * 4 + ((j < 4) ? j : 60 + j);
            float v = acc[i][j] + bias[col];
            if (relu) v = fmaxf(v, 0.f);
            C[(long long)row * MD + col] = v;
        }
    }
}

// ---------------- split fp32 -> bf16 hi + lo ----------------
__global__ void split_bf16(const float* __restrict__ f1, const float* __restrict__ f2,
                           __nv_bfloat16* __restrict__ h1, __nv_bfloat16* __restrict__ l1,
                           __nv_bfloat16* __restrict__ h2, __nv_bfloat16* __restrict__ l2)
{
    int i = blockIdx.x * 256 + threadIdx.x;
    {
        float x = f1[i];
        __nv_bfloat16 h = __float2bfloat16(x);
        h1[i] = h;
        l1[i] = __float2bfloat16(x - __bfloat162float(h));
    }
    {
        float x = f2[i];
        __nv_bfloat16 h = __float2bfloat16(x);
        h2[i] = h;
        l2[i] = __float2bfloat16(x - __bfloat162float(h));
    }
}

// ---------------- scores via mma.sync bf16 (2-way split, 3 passes) ---------
// Double-buffered smem: next chunk's global loads issue before compute.
__device__ __forceinline__ void mma16816(float* c, const uint32_t* a, const uint32_t* b)
{
    asm volatile(
        "mma.sync.aligned.m16n8k16.row.col.f32.bf16.bf16.f32 "
        "{%0,%1,%2,%3}, {%4,%5,%6,%7}, {%8,%9}, {%0,%1,%2,%3};"
        : "+f"(c[0]), "+f"(c[1]), "+f"(c[2]), "+f"(c[3])
        : "r"(a[0]), "r"(a[1]), "r"(a[2]), "r"(a[3]), "r"(b[0]), "r"(b[1]));
}

__global__ __launch_bounds__(256, 1)
void mma_scores(const __nv_bfloat16* __restrict__ Ah, const __nv_bfloat16* __restrict__ Al,
                const __nv_bfloat16* __restrict__ Bh, const __nv_bfloat16* __restrict__ Bl,
                float* __restrict__ C)
{
    __shared__ __nv_bfloat16 As[2][128][40];   // stride 40: conflict-free frags
    __shared__ __nv_bfloat16 Bs[2][128][40];

    const int bz = blockIdx.z;
    const int m0 = blockIdx.y * 128, n0 = blockIdx.x * 128;
    const size_t base = (size_t)bz * NQ * MD;
    const int tid = threadIdx.x, warp = tid >> 5, lane = tid & 31;
    const int wm = (warp >> 2) * 64, wn = (warp & 3) * 32;

    float acc[4][4][4];
#pragma unroll
    for (int mi = 0; mi < 4; mi++)
#pragma unroll
        for (int ni = 0; ni < 4; ni++)
#pragma unroll
            for (int q = 0; q < 4; q++) acc[mi][ni][q] = 0.f;

    const int lrow = tid >> 1;            // 0..127
    const int loff = (tid & 1) * 16;      // 0 or 16 halves

    const __nv_bfloat16* Aps[3] = { Ah + base + (size_t)m0 * MD,
                                    Ah + base + (size_t)m0 * MD,
                                    Al + base + (size_t)m0 * MD };
    const __nv_bfloat16* Bps[3] = { Bh + base + (size_t)n0 * MD,
                                    Bl + base + (size_t)n0 * MD,
                                    Bh + base + (size_t)n0 * MD };

    uint4 ra0, ra1, rb0, rb1;
    // chunk c: p = c>>3, kk = (c&7)*32; 24 chunks total
    {
        const __nv_bfloat16* Ag = Aps[0];
        const __nv_bfloat16* Bg = Bps[0];
        const uint4* ga = (const uint4*)(Ag + (size_t)lrow * MD + loff);
        const uint4* gb = (const uint4*)(Bg + (size_t)lrow * MD + loff);
        ra0 = ga[0]; ra1 = ga[1];
        rb0 = gb[0]; rb1 = gb[1];
    }
    *(uint4*)&As[0][lrow][loff]     = ra0;
    *(uint4*)&As[0][lrow][loff + 8] = ra1;
    *(uint4*)&Bs[0][lrow][loff]     = rb0;
    *(uint4*)&Bs[0][lrow][loff + 8] = rb1;
    __syncthreads();

#pragma unroll 1
    for (int c = 0; c < 24; c++) {
        const int cur = c & 1;
        if (c + 1 < 24) {
            int p = (c + 1) >> 3, kk = ((c + 1) & 7) * 32;
            const uint4* ga = (const uint4*)(Aps[p] + (size_t)lrow * MD + kk + loff);
            const uint4* gb = (const uint4*)(Bps[p] + (size_t)lrow * MD + kk + loff);
            ra0 = ga[0]; ra1 = ga[1];
            rb0 = gb[0]; rb1 = gb[1];
        }
#pragma unroll
        for (int ks = 0; ks < 32; ks += 16) {
            uint32_t afr[4][4], bfr[4][2];
            const int fr = lane >> 2, fc = ks + (lane & 3) * 2;
#pragma unroll
            for (int mi = 0; mi < 4; mi++) {
                int r = wm + mi * 16 + fr;
                afr[mi][0] = *(const uint32_t*)&As[cur][r][fc];
                afr[mi][1] = *(const uint32_t*)&As[cur][r + 8][fc];
                afr[mi][2] = *(const uint32_t*)&As[cur][r][fc + 8];
                afr[mi][3] = *(const uint32_t*)&As[cur][r + 8][fc + 8];
            }
#pragma unroll
            for (int ni = 0; ni < 4; ni++) {
                int r = wn + ni * 8 + fr;
                bfr[ni][0] = *(const uint32_t*)&Bs[cur][r][fc];
                bfr[ni][1] = *(const uint32_t*)&Bs[cur][r][fc + 8];
            }
#pragma unroll
            for (int mi = 0; mi < 4; mi++)
#pragma unroll
                for (int ni = 0; ni < 4; ni++)
                    mma16816(acc[mi][ni], afr[mi], bfr[ni]);
        }
        if (c + 1 < 24) {
            const int nxt = (c + 1) & 1;
            __syncthreads();
            *(uint4*)&As[nxt][lrow][loff]     = ra0;
            *(uint4*)&As[nxt][lrow][loff + 8] = ra1;
            *(uint4*)&Bs[nxt][lrow][loff]     = rb0;
            *(uint4*)&Bs[nxt][lrow][loff + 8] = rb1;
            __syncthreads();
        }
    }

    // epilogue: out[row * NP + col] = acc / 16
    float* Cb = C + (size_t)bz * NP * NP;
#pragma unroll
    for (int mi = 0; mi < 4; mi++) {
        int r0 = m0 + wm + mi * 16 + (lane >> 2);
#pragma unroll
        for (int ni = 0; ni < 4; ni++) {
            int c0 = n0 + wn + ni * 8 + (lane & 3) * 2;
            Cb[(size_t)r0 * NP + c0]           = acc[mi][ni][0] * 0.0625f;
            Cb[(size_t)r0 * NP + c0 + 1]       = acc[mi][ni][1] * 0.0625f;
            Cb[(size_t)(r0 + 8) * NP + c0]     = acc[mi][ni][2] * 0.0625f;
            Cb[(size_t)(r0 + 8) * NP + c0 + 1] = acc[mi][ni][3] * 0.0625f;
        }
    }
}

// -------- exp + dustbin fill + transpose: S (in d_out) -> Kh, KT -----------
__global__ void expk_kernel(float* __restrict__ S, const float* __restrict__ bin,
                            __half* __restrict__ Kh, __half* __restrict__ KT)
{
    __shared__ float tile[32][33];
    const int b  = blockIdx.z;
    const int i0 = blockIdx.y * 32, j0 = blockIdx.x * 32;
    const float alpha = *bin;
    float*  Sb  = S  + (size_t)b * NP * NP;
    __half* Khb = Kh + (size_t)b * NP * STR;
    __half* KTb = KT + (size_t)b * NP * STR;
    const int tx = threadIdx.x, ty0 = threadIdx.y;
#pragma unroll
    for (int q = 0; q < 4; q++) {
        int ty = ty0 + q * 8;
        int i = i0 + ty, j = j0 + tx;
        if (i < NP && j < NP) {
            float s;
            if (i < NP - 1 && j < NP - 1) {
                s = Sb[(size_t)i * NP + j];
            } else {
                s = alpha;
                Sb[(size_t)i * NP + j] = alpha;   // dustbin for final pass
            }
            float e = expf(s);
            tile[ty][tx] = e;
            Khb[(size_t)i * STR + j] = __float2half(e);
        }
    }
    __syncthreads();
#pragma unroll
    for (int q = 0; q < 4; q++) {
        int ty = ty0 + q * 8;
        int i = i0 + tx, j = j0 + ty;
        if (i < NP && j < NP)
            KTb[(size_t)j * STR + i] = __float2half(tile[tx][ty]);
    }
}

// ---------------- barrier flag reset (per graph replay) ----------------
__global__ void reset_bar()
{
    int i = threadIdx.x;
    if (i < NB * 64) ((volatile int*)g_flag)[i] = 0;
}

// ---------------- per-batch flag barrier (no atomics) ----------------
// Each block STGs its own flag = step; threads 0..36 poll the 37 flags in
// parallel (distinct addresses). __threadfence before the flag write orders
// this block's data writes; polling reads are volatile (L2-visible).
__device__ __forceinline__ void batch_barrier(int batch, int sub, int step)
{
    __syncthreads();
    if (threadIdx.x == 0) {
        __threadfence();
        g_flag[batch][sub] = step;
    }
    if (threadIdx.x < SUBB) {
        while (g_flag[batch][threadIdx.x] < step) { }
    }
    __syncthreads();
}

// ---------------- one Sinkhorn half-pass for this block's rows ------------
__device__ __forceinline__ void half_pass(const __half* __restrict__ Km,
                                          const float* __restrict__ x,
                                          float* __restrict__ y,
                                          int batch, int sub, float* xs)
{
    // stage x[batch] into smem (XOR granule swizzle); __ldcv -> L2-fresh
    const float* xb = x + batch * STR;
    for (int i = threadIdx.x; i < NP; i += 1024) {
        int g = i >> 2, o = i & 3;
        int sg = g ^ ((g >> 3) & 1);
        xs[(sg << 2) | o] = __ldcv(&xb[i]);
    }
    __syncthreads();

    const int w = threadIdx.x >> 5, lane = threadIdx.x & 31;
    const float4* xs4 = (const float4*)xs;

    for (int rr = w; rr < RPB; rr += 32) {   // NO unroll: keep kv[8] regs low
        int row = sub * RPB + rr;
        if (row >= NP) break;
        const float4* kr = (const float4*)(Km + (size_t)batch * NP * STR
                                              + (size_t)row * STR);
        float4 kv[8];
#pragma unroll
        for (int i = 0; i < 8; i++) kv[i] = kr[i * 32 + lane];

        float s = 0.f;
#pragma unroll
        for (int i = 0; i < 8; i++) {
            const __half2* h = (const __half2*)&kv[i];
            int g0 = (i * 32 + lane) * 2;
            int sw = (g0 >> 3) & 1;
            float4 x0 = xs4[g0 ^ sw];
            float4 x1 = xs4[(g0 | 1) ^ sw];
            float2 f0 = __half22float2(h[0]);
            float2 f1 = __half22float2(h[1]);
            float2 f2 = __half22float2(h[2]);
            float2 f3 = __half22float2(h[3]);
            s = fmaf(f0.x, x0.x, s); s = fmaf(f0.y, x0.y, s);
            s = fmaf(f1.x, x0.z, s); s = fmaf(f1.y, x0.w, s);
            s = fmaf(f2.x, x1.x, s); s = fmaf(f2.y, x1.y, s);
            s = fmaf(f3.x, x1.z, s); s = fmaf(f3.y, x1.w, s);
        }
        if (lane == 0)
            s += __half2float(((const __half*)kr)[2048]) * xs[2048];
#pragma unroll
        for (int o = 16; o; o >>= 1) s += __shfl_xor_sync(0xffffffffu, s, o);
        if (lane == 0) {
            float mu = (row < NQ) ? (1.0f / 4096.0f) : 0.5f;
            y[batch * STR + row] = mu / s;
        }
    }
}

// ---------------- persistent Sinkhorn: 100 iterations, one launch ----------
__global__ __launch_bounds__(1024, 1)
void sink_persist(const __half* __restrict__ Kh, const __half* __restrict__ KT,
                  float* __restrict__ a, float* __restrict__ bv)
{
    __shared__ __align__(16) float xs[2056];
    const int bl = blockIdx.x;
    const int batch = bl / SUBB, sub = bl % SUBB;

    // init bv = 1 on my row slice
    for (int rr = threadIdx.x; rr < RPB; rr += 1024) {
        int row = sub * RPB + rr;
        if (row < NP) bv[batch * STR + row] = 1.0f;
    }

    int step = 1;
    batch_barrier(batch, sub, step++);
    for (int it = 0; it < 100; it++) {
        half_pass(Kh, bv, a, batch, sub, xs);
        batch_barrier(batch, sub, step++);
        half_pass(KT, a, bv, batch, sub, xs);
        batch_barrier(batch, sub, step++);
    }
}

// ---------------- final: out = exp(S) * a_i * b_j * (m+n), in place --------
__global__ void final_kernel(float* __restrict__ out,
                             const float* __restrict__ a,
                             const float* __restrict__ bv)
{
    const int b = blockIdx.y;
    const int row = blockIdx.x;
    const float av = a[b * STR + row] * 4096.0f;
    float* o = out + (size_t)b * NP * NP + (size_t)row * NP;
    const float* bb = bv + b * STR;
    for (int j = threadIdx.x; j < NP; j += 256)
        o[j] = expf(o[j]) * av * bb[j];
}

// ---------------- launch ----------------
extern "C" void kernel_launch(void* const* d_in, const int* in_sizes, int n_in,
                              void* d_out, int out_size)
{
    const float* Xlc  = (const float*)d_in[0];
    const float* Xte  = (const float*)d_in[1];
    const float* W1lc = (const float*)d_in[2];
    const float* b1lc = (const float*)d_in[3];
    const float* W2lc = (const float*)d_in[4];
    const float* b2lc = (const float*)d_in[5];
    const float* W1te = (const float*)d_in[6];
    const float* b1te = (const float*)d_in[7];
    const float* W2te = (const float*)d_in[8];
    const float* b2te = (const float*)d_in[9];
    const float* bin  = (const float*)d_in[10];
    float* out = (float*)d_out;

    float *f1, *f2, *h1, *h2, *a, *bv;
    __half *Kh, *KT;
    __nv_bfloat16 *s1h, *s1l, *s2h, *s2l;
    cudaGetSymbolAddress((void**)&f1, g_f1);
    cudaGetSymbolAddress((void**)&f2, g_f2);
    cudaGetSymbolAddress((void**)&h1, g_h1);
    cudaGetSymbolAddress((void**)&h2, g_h2);
    cudaGetSymbolAddress((void**)&a,  g_a);
    cudaGetSymbolAddress((void**)&bv, g_bv);
    cudaGetSymbolAddress((void**)&Kh, g_Kh);
    cudaGetSymbolAddress((void**)&KT, g_KT);
    cudaGetSymbolAddress((void**)&s1h, g_s1h);
    cudaGetSymbolAddress((void**)&s1l, g_s1l);
    cudaGetSymbolAddress((void**)&s2h, g_s2h);
    cudaGetSymbolAddress((void**)&s2l, g_s2l);

    // MLPs: layer1 (relu) for lc+te in one launch, then layer2
    dim3 gMLP(2, 64, 2);
    {
        MlpArgs a1;
        a1.A[0] = Xlc; a1.B[0] = W1lc; a1.bias[0] = b1lc; a1.C[0] = h1;
        a1.A[1] = Xte; a1.B[1] = W1te; a1.bias[1] = b1te; a1.C[1] = h2;
        sgemm_mlp<<<gMLP, 256>>>(a1, 1);
        MlpArgs a2;
        a2.A[0] = h1; a2.B[0] = W2lc; a2.bias[0] = b2lc; a2.C[0] = f1;
        a2.A[1] = h2; a2.B[1] = W2te; a2.bias[1] = b2te; a2.C[1] = f2;
        sgemm_mlp<<<gMLP, 256>>>(a2, 0);
    }

    // split f1/f2 into bf16 hi/lo
    split_bf16<<<(NB * NQ * MD) / 256, 256>>>(f1, f2, s1h, s1l, s2h, s2l);

    // scores via tensor cores: 3-pass split bf16, fp32 accum, into d_out
    mma_scores<<<dim3(16, 16, NB), 256>>>(s1h, s1l, s2h, s2l, out);

    // exp + dustbin + transpose
    expk_kernel<<<dim3(65, 65, NB), dim3(32, 8)>>>(out, bin, Kh, KT);

    // Sinkhorn: persistent kernel, per-batch flag barriers
    reset_bar<<<1, 256>>>();
    sink_persist<<<NBLK, 1024>>>(Kh, KT, a, bv);

    // out = exp(S) * a_i * b_j * (m+n)
    final_kernel<<<dim3(NP, NB), 256>>>(out, a, bv);
}

// round 9
// speedup vs baseline: 1.5283x; 1.5283x over previous
#include <cuda_runtime.h>
#include <cuda_fp16.h>
#include <cuda_bf16.h>
#include <stdint.h>

// Problem constants
#define NB   4        // batches
#define NQ   2048     // N_LC = N_TE
#define NP   2049     // NQ + dustbin
#define MD   256      // feature dim D
#define STR  2064     // padded row stride (elements) for K matrices / vectors

// Persistent sink config: 148 blocks, 37/batch, 56 rows/block
#define NBLK 148
#define SUBB 37
#define RPB  56

// ---------------- device scratch (static, no allocation) ----------------
static __device__ __half g_Kh[(size_t)NB * NP * STR];   // exp(Z), row-major, fp16
static __device__ __half g_KT[(size_t)NB * NP * STR];   // exp(Z)^T, fp16
static __device__ float  g_f1[(size_t)NB * NQ * MD];    // MLP(lc) output
static __device__ float  g_f2[(size_t)NB * NQ * MD];    // MLP(te) output
static __device__ float  g_h1[(size_t)NB * NQ * MD];    // hidden lc
static __device__ float  g_h2[(size_t)NB * NQ * MD];    // hidden te
static __device__ __nv_bfloat16 g_s1h[(size_t)NB * NQ * MD];  // f1 split hi
static __device__ __nv_bfloat16 g_s1l[(size_t)NB * NQ * MD];  // f1 split lo
static __device__ __nv_bfloat16 g_s2h[(size_t)NB * NQ * MD];  // f2 split hi
static __device__ __nv_bfloat16 g_s2l[(size_t)NB * NQ * MD];  // f2 split lo
static __device__ float  g_a [NB * STR];                // scaling vec a
static __device__ float  g_bv[NB * STR];                // scaling vec b
static __device__ unsigned g_bar_cnt;                   // grid barrier arrivals
static __device__ unsigned g_bar_epoch;                 // grid barrier epoch

// ---------------- MLP GEMM: 2 pointer sets selected by blockIdx.z ----------
struct MlpArgs {
    const float* A[2];
    const float* B[2];
    const float* bias[2];
    float* C[2];
};

__global__ __launch_bounds__(256, 2)
void sgemm_mlp(MlpArgs args, int relu)
{
    __shared__ float As[8][128];
    __shared__ float Bs[8][128];
    const int z = blockIdx.z;
    const float* A = args.A[z];
    const float* B = args.B[z];
    const float* bias = args.bias[z];
    float* C = args.C[z];
    const int K = MD;

    const int tid = threadIdx.x;
    const int tx = tid & 15, ty = tid >> 4;
    const int brow = blockIdx.y << 7;
    const int bcol = blockIdx.x << 7;
    const int lr = tid >> 1;
    const int lk = (tid & 1) << 2;

    const float* Ald = A + (long long)(brow + lr) * K + lk;
    const float* Bld = B + (long long)(bcol + lr) * K + lk;

    float acc[8][8];
#pragma unroll
    for (int i = 0; i < 8; i++)
#pragma unroll
        for (int j = 0; j < 8; j++) acc[i][j] = 0.f;

    for (int kk = 0; kk < K; kk += 8) {
        float4 av = *(const float4*)(Ald + kk);
        float4 bv = *(const float4*)(Bld + kk);
        __syncthreads();
        As[lk + 0][lr] = av.x; As[lk + 1][lr] = av.y;
        As[lk + 2][lr] = av.z; As[lk + 3][lr] = av.w;
        Bs[lk + 0][lr] = bv.x; Bs[lk + 1][lr] = bv.y;
        Bs[lk + 2][lr] = bv.z; Bs[lk + 3][lr] = bv.w;
        __syncthreads();
#pragma unroll
        for (int k = 0; k < 8; k++) {
            float ar[8], br[8];
            *(float4*)&ar[0] = *(const float4*)&As[k][ty * 4];
            *(float4*)&ar[4] = *(const float4*)&As[k][ty * 4 + 64];
            *(float4*)&br[0] = *(const float4*)&Bs[k][tx * 4];
            *(float4*)&br[4] = *(const float4*)&Bs[k][tx * 4 + 64];
#pragma unroll
            for (int i = 0; i < 8; i++)
#pragma unroll
                for (int j = 0; j < 8; j++)
                    acc[i][j] = fmaf(ar[i], br[j], acc[i][j]);
        }
    }

#pragma unroll
    for (int i = 0; i < 8; i++) {
        int row = brow + ty * 4 + ((i < 4) ? i : 60 + i);
#pragma unroll
        for (int j = 0; j < 8; j++) {
            int col = bcol + tx * 4 + ((j < 4) ? j : 60 + j);
            float v = acc[i][j] + bias[col];
            if (relu) v = fmaxf(v, 0.f);
            C[(long long)row * MD + col] = v;
        }
    }
}

// ---------------- split fp32 -> bf16 hi + lo ----------------
__global__ void split_bf16(const float* __restrict__ f1, const float* __restrict__ f2,
                           __nv_bfloat16* __restrict__ h1, __nv_bfloat16* __restrict__ l1,
                           __nv_bfloat16* __restrict__ h2, __nv_bfloat16* __restrict__ l2)
{
    int i = blockIdx.x * 256 + threadIdx.x;
    {
        float x = f1[i];
        __nv_bfloat16 h = __float2bfloat16(x);
        h1[i] = h;
        l1[i] = __float2bfloat16(x - __bfloat162float(h));
    }
    {
        float x = f2[i];
        __nv_bfloat16 h = __float2bfloat16(x);
        h2[i] = h;
        l2[i] = __float2bfloat16(x - __bfloat162float(h));
    }
}

// ---------------- scores via mma.sync bf16 (2-way split, 3 passes) ---------
// Double-buffered smem: next chunk's global loads issue before compute.
__device__ __forceinline__ void mma16816(float* c, const uint32_t* a, const uint32_t* b)
{
    asm volatile(
        "mma.sync.aligned.m16n8k16.row.col.f32.bf16.bf16.f32 "
        "{%0,%1,%2,%3}, {%4,%5,%6,%7}, {%8,%9}, {%0,%1,%2,%3};"
        : "+f"(c[0]), "+f"(c[1]), "+f"(c[2]), "+f"(c[3])
        : "r"(a[0]), "r"(a[1]), "r"(a[2]), "r"(a[3]), "r"(b[0]), "r"(b[1]));
}

__global__ __launch_bounds__(256, 1)
void mma_scores(const __nv_bfloat16* __restrict__ Ah, const __nv_bfloat16* __restrict__ Al,
                const __nv_bfloat16* __restrict__ Bh, const __nv_bfloat16* __restrict__ Bl,
                float* __restrict__ C)
{
    __shared__ __nv_bfloat16 As[2][128][40];   // stride 40: conflict-free frags
    __shared__ __nv_bfloat16 Bs[2][128][40];

    const int bz = blockIdx.z;
    const int m0 = blockIdx.y * 128, n0 = blockIdx.x * 128;
    const size_t base = (size_t)bz * NQ * MD;
    const int tid = threadIdx.x, warp = tid >> 5, lane = tid & 31;
    const int wm = (warp >> 2) * 64, wn = (warp & 3) * 32;

    float acc[4][4][4];
#pragma unroll
    for (int mi = 0; mi < 4; mi++)
#pragma unroll
        for (int ni = 0; ni < 4; ni++)
#pragma unroll
            for (int q = 0; q < 4; q++) acc[mi][ni][q] = 0.f;

    const int lrow = tid >> 1;            // 0..127
    const int loff = (tid & 1) * 16;      // 0 or 16 halves

    const __nv_bfloat16* Aps[3] = { Ah + base + (size_t)m0 * MD,
                                    Ah + base + (size_t)m0 * MD,
                                    Al + base + (size_t)m0 * MD };
    const __nv_bfloat16* Bps[3] = { Bh + base + (size_t)n0 * MD,
                                    Bl + base + (size_t)n0 * MD,
                                    Bh + base + (size_t)n0 * MD };

    uint4 ra0, ra1, rb0, rb1;
    // chunk c: p = c>>3, kk = (c&7)*32; 24 chunks total
    {
        const uint4* ga = (const uint4*)(Aps[0] + (size_t)lrow * MD + loff);
        const uint4* gb = (const uint4*)(Bps[0] + (size_t)lrow * MD + loff);
        ra0 = ga[0]; ra1 = ga[1];
        rb0 = gb[0]; rb1 = gb[1];
    }
    *(uint4*)&As[0][lrow][loff]     = ra0;
    *(uint4*)&As[0][lrow][loff + 8] = ra1;
    *(uint4*)&Bs[0][lrow][loff]     = rb0;
    *(uint4*)&Bs[0][lrow][loff + 8] = rb1;
    __syncthreads();

#pragma unroll 1
    for (int c = 0; c < 24; c++) {
        const int cur = c & 1;
        if (c + 1 < 24) {
            int p = (c + 1) >> 3, kk = ((c + 1) & 7) * 32;
            const uint4* ga = (const uint4*)(Aps[p] + (size_t)lrow * MD + kk + loff);
            const uint4* gb = (const uint4*)(Bps[p] + (size_t)lrow * MD + kk + loff);
            ra0 = ga[0]; ra1 = ga[1];
            rb0 = gb[0]; rb1 = gb[1];
        }
#pragma unroll
        for (int ks = 0; ks < 32; ks += 16) {
            uint32_t afr[4][4], bfr[4][2];
            const int fr = lane >> 2, fc = ks + (lane & 3) * 2;
#pragma unroll
            for (int mi = 0; mi < 4; mi++) {
                int r = wm + mi * 16 + fr;
                afr[mi][0] = *(const uint32_t*)&As[cur][r][fc];
                afr[mi][1] = *(const uint32_t*)&As[cur][r + 8][fc];
                afr[mi][2] = *(const uint32_t*)&As[cur][r][fc + 8];
                afr[mi][3] = *(const uint32_t*)&As[cur][r + 8][fc + 8];
            }
#pragma unroll
            for (int ni = 0; ni < 4; ni++) {
                int r = wn + ni * 8 + fr;
                bfr[ni][0] = *(const uint32_t*)&Bs[cur][r][fc];
                bfr[ni][1] = *(const uint32_t*)&Bs[cur][r][fc + 8];
            }
#pragma unroll
            for (int mi = 0; mi < 4; mi++)
#pragma unroll
                for (int ni = 0; ni < 4; ni++)
                    mma16816(acc[mi][ni], afr[mi], bfr[ni]);
        }
        if (c + 1 < 24) {
            const int nxt = (c + 1) & 1;
            __syncthreads();
            *(uint4*)&As[nxt][lrow][loff]     = ra0;
            *(uint4*)&As[nxt][lrow][loff + 8] = ra1;
            *(uint4*)&Bs[nxt][lrow][loff]     = rb0;
            *(uint4*)&Bs[nxt][lrow][loff + 8] = rb1;
            __syncthreads();
        }
    }

    // epilogue: out[row * NP + col] = acc / 16
    float* Cb = C + (size_t)bz * NP * NP;
#pragma unroll
    for (int mi = 0; mi < 4; mi++) {
        int r0 = m0 + wm + mi * 16 + (lane >> 2);
#pragma unroll
        for (int ni = 0; ni < 4; ni++) {
            int c0 = n0 + wn + ni * 8 + (lane & 3) * 2;
            Cb[(size_t)r0 * NP + c0]           = acc[mi][ni][0] * 0.0625f;
            Cb[(size_t)r0 * NP + c0 + 1]       = acc[mi][ni][1] * 0.0625f;
            Cb[(size_t)(r0 + 8) * NP + c0]     = acc[mi][ni][2] * 0.0625f;
            Cb[(size_t)(r0 + 8) * NP + c0 + 1] = acc[mi][ni][3] * 0.0625f;
        }
    }
}

// -------- exp + dustbin fill + transpose: S (in d_out) -> Kh, KT -----------
__global__ void expk_kernel(float* __restrict__ S, const float* __restrict__ bin,
                            __half* __restrict__ Kh, __half* __restrict__ KT)
{
    __shared__ float tile[32][33];
    const int b  = blockIdx.z;
    const int i0 = blockIdx.y * 32, j0 = blockIdx.x * 32;
    const float alpha = *bin;
    float*  Sb  = S  + (size_t)b * NP * NP;
    __half* Khb = Kh + (size_t)b * NP * STR;
    __half* KTb = KT + (size_t)b * NP * STR;
    const int tx = threadIdx.x, ty0 = threadIdx.y;
#pragma unroll
    for (int q = 0; q < 4; q++) {
        int ty = ty0 + q * 8;
        int i = i0 + ty, j = j0 + tx;
        if (i < NP && j < NP) {
            float s;
            if (i < NP - 1 && j < NP - 1) {
                s = Sb[(size_t)i * NP + j];
            } else {
                s = alpha;
                Sb[(size_t)i * NP + j] = alpha;   // dustbin for final pass
            }
            float e = expf(s);
            tile[ty][tx] = e;
            Khb[(size_t)i * STR + j] = __float2half(e);
        }
    }
    __syncthreads();
#pragma unroll
    for (int q = 0; q < 4; q++) {
        int ty = ty0 + q * 8;
        int i = i0 + tx, j = j0 + ty;
        if (i < NP && j < NP)
            KTb[(size_t)j * STR + i] = __float2half(tile[tx][ty]);
    }
}

// ---------------- barrier state reset (per graph replay) ----------------
__global__ void reset_bar()
{
    g_bar_cnt = 0;
    g_bar_epoch = 0;
}

// ---------------- grid barrier (R6): single atomic counter + epoch --------
__device__ __forceinline__ void grid_barrier(unsigned k)
{
    __syncthreads();
    if (threadIdx.x == 0) {
        __threadfence();
        unsigned t = atomicAdd(&g_bar_cnt, 1u);
        if (t == (k + 1u) * NBLK - 1u) {
            atomicAdd(&g_bar_epoch, 1u);    // epoch -> k+1
        } else {
            while (*(volatile unsigned*)&g_bar_epoch <= k) { }
        }
        __threadfence();
    }
    __syncthreads();
}

// ---------------- one Sinkhorn half-pass for this block's rows ------------
// Each warp fuses its two rows (w, w+32): x chunks loaded from smem ONCE and
// applied to both rows' K -> halves LDS traffic on the L1tex path.
__device__ __forceinline__ void half_pass(const __half* __restrict__ Km,
                                          const float* __restrict__ x,
                                          float* __restrict__ y,
                                          int batch, int sub, float* xs)
{
    // stage x[batch] into smem with XOR granule swizzle (involution map)
    const float* xb = x + batch * STR;
    for (int i = threadIdx.x; i < NP; i += 1024) {
        int g = i >> 2, o = i & 3;
        int sg = g ^ ((g >> 3) & 1);
        xs[(sg << 2) | o] = xb[i];
    }
    __syncthreads();

    const int w = threadIdx.x >> 5, lane = threadIdx.x & 31;
    const float4* xs4 = (const float4*)xs;

    const int rowbase = sub * RPB;
    const int nrows = min(RPB, NP - rowbase);      // 56; last block: 33
    const int rowA = rowbase + w;                  // always valid (w<32<=nrows)
    const bool hasB = (w + 32) < nrows;
    const int rowB = rowA + (hasB ? 32 : 0);       // dummy = rowA when absent

    const float4* krA = (const float4*)(Km + (size_t)batch * NP * STR
                                           + (size_t)rowA * STR);
    const float4* krB = (const float4*)(Km + (size_t)batch * NP * STR
                                           + (size_t)rowB * STR);

    float sA0 = 0.f, sA1 = 0.f, sB0 = 0.f, sB1 = 0.f;
#pragma unroll 2
    for (int c = 0; c < 8; c++) {
        float4 kA = krA[c * 32 + lane];
        float4 kB = krB[c * 32 + lane];
        int g0 = (c * 32 + lane) * 2;
        int sw = (g0 >> 3) & 1;
        float4 x0 = xs4[g0 ^ sw];
        float4 x1 = xs4[(g0 | 1) ^ sw];
        const __half2* hA = (const __half2*)&kA;
        const __half2* hB = (const __half2*)&kB;
        {
            float2 f0 = __half22float2(hA[0]);
            float2 f1 = __half22float2(hA[1]);
            float2 f2 = __half22float2(hA[2]);
            float2 f3 = __half22float2(hA[3]);
            sA0 = fmaf(f0.x, x0.x, sA0); sA1 = fmaf(f0.y, x0.y, sA1);
            sA0 = fmaf(f1.x, x0.z, sA0); sA1 = fmaf(f1.y, x0.w, sA1);
            sA0 = fmaf(f2.x, x1.x, sA0); sA1 = fmaf(f2.y, x1.y, sA1);
            sA0 = fmaf(f3.x, x1.z, sA0); sA1 = fmaf(f3.y, x1.w, sA1);
        }
        {
            float2 f0 = __half22float2(hB[0]);
            float2 f1 = __half22float2(hB[1]);
            float2 f2 = __half22float2(hB[2]);
            float2 f3 = __half22float2(hB[3]);
            sB0 = fmaf(f0.x, x0.x, sB0); sB1 = fmaf(f0.y, x0.y, sB1);
            sB0 = fmaf(f1.x, x0.z, sB0); sB1 = fmaf(f1.y, x0.w, sB1);
            sB0 = fmaf(f2.x, x1.x, sB0); sB1 = fmaf(f2.y, x1.y, sB1);
            sB0 = fmaf(f3.x, x1.z, sB0); sB1 = fmaf(f3.y, x1.w, sB1);
        }
    }
    float sA = sA0 + sA1;
    float sB = sB0 + sB1;
    if (lane == 0) {
        const __half* KbA = (const __half*)krA;
        sA += __half2float(KbA[2048]) * xs[2048];
        if (hasB) {
            const __half* KbB = (const __half*)krB;
            sB += __half2float(KbB[2048]) * xs[2048];
        }
    }
#pragma unroll
    for (int o = 16; o; o >>= 1) {
        sA += __shfl_xor_sync(0xffffffffu, sA, o);
        sB += __shfl_xor_sync(0xffffffffu, sB, o);
    }
    if (lane == 0) {
        float muA = (rowA < NQ) ? (1.0f / 4096.0f) : 0.5f;
        y[batch * STR + rowA] = muA / sA;
        if (hasB) {
            float muB = (rowB < NQ) ? (1.0f / 4096.0f) : 0.5f;
            y[batch * STR + rowB] = muB / sB;
        }
    }
}

// ---------------- persistent Sinkhorn: 100 iterations, one launch ----------
__global__ __launch_bounds__(1024, 1)
void sink_persist(const __half* __restrict__ Kh, const __half* __restrict__ KT,
                  float* __restrict__ a, float* __restrict__ bv)
{
    __shared__ __align__(16) float xs[2056];
    const int bl = blockIdx.x;
    const int batch = bl / SUBB, sub = bl % SUBB;

    // init bv = 1 on my row slice
    for (int rr = threadIdx.x; rr < RPB; rr += 1024) {
        int row = sub * RPB + rr;
        if (row < NP) bv[batch * STR + row] = 1.0f;
    }

    unsigned bk = 0;
    grid_barrier(bk++);
    for (int it = 0; it < 100; it++) {
        half_pass(Kh, bv, a, batch, sub, xs);
        grid_barrier(bk++);
        half_pass(KT, a, bv, batch, sub, xs);
        grid_barrier(bk++);
    }
}

// ---------------- final: out = exp(S) * a_i * b_j * (m+n), in place --------
__global__ void final_kernel(float* __restrict__ out,
                             const float* __restrict__ a,
                             const float* __restrict__ bv)
{
    const int b = blockIdx.y;
    const int row = blockIdx.x;
    const float av = a[b * STR + row] * 4096.0f;
    float* o = out + (size_t)b * NP * NP + (size_t)row * NP;
    const float* bb = bv + b * STR;
    for (int j = threadIdx.x; j < NP; j += 256)
        o[j] = expf(o[j]) * av * bb[j];
}

// ---------------- launch ----------------
extern "C" void kernel_launch(void* const* d_in, const int* in_sizes, int n_in,
                              void* d_out, int out_size)
{
    const float* Xlc  = (const float*)d_in[0];
    const float* Xte  = (const float*)d_in[1];
    const float* W1lc = (const float*)d_in[2];
    const float* b1lc = (const float*)d_in[3];
    const float* W2lc = (const float*)d_in[4];
    const float* b2lc = (const float*)d_in[5];
    const float* W1te = (const float*)d_in[6];
    const float* b1te = (const float*)d_in[7];
    const float* W2te = (const float*)d_in[8];
    const float* b2te = (const float*)d_in[9];
    const float* bin  = (const float*)d_in[10];
    float* out = (float*)d_out;

    float *f1, *f2, *h1, *h2, *a, *bv;
    __half *Kh, *KT;
    __nv_bfloat16 *s1h, *s1l, *s2h, *s2l;
    cudaGetSymbolAddress((void**)&f1, g_f1);
    cudaGetSymbolAddress((void**)&f2, g_f2);
    cudaGetSymbolAddress((void**)&h1, g_h1);
    cudaGetSymbolAddress((void**)&h2, g_h2);
    cudaGetSymbolAddress((void**)&a,  g_a);
    cudaGetSymbolAddress((void**)&bv, g_bv);
    cudaGetSymbolAddress((void**)&Kh, g_Kh);
    cudaGetSymbolAddress((void**)&KT, g_KT);
    cudaGetSymbolAddress((void**)&s1h, g_s1h);
    cudaGetSymbolAddress((void**)&s1l, g_s1l);
    cudaGetSymbolAddress((void**)&s2h, g_s2h);
    cudaGetSymbolAddress((void**)&s2l, g_s2l);

    // MLPs: layer1 (relu) for lc+te in one launch, then layer2
    dim3 gMLP(2, 64, 2);
    {
        MlpArgs a1;
        a1.A[0] = Xlc; a1.B[0] = W1lc; a1.bias[0] = b1lc; a1.C[0] = h1;
        a1.A[1] = Xte; a1.B[1] = W1te; a1.bias[1] = b1te; a1.C[1] = h2;
        sgemm_mlp<<<gMLP, 256>>>(a1, 1);
        MlpArgs a2;
        a2.A[0] = h1; a2.B[0] = W2lc; a2.bias[0] = b2lc; a2.C[0] = f1;
        a2.A[1] = h2; a2.B[1] = W2te; a2.bias[1] = b2te; a2.C[1] = f2;
        sgemm_mlp<<<gMLP, 256>>>(a2, 0);
    }

    // split f1/f2 into bf16 hi/lo
    split_bf16<<<(NB * NQ * MD) / 256, 256>>>(f1, f2, s1h, s1l, s2h, s2l);

    // scores via tensor cores: 3-pass split bf16, fp32 accum, into d_out
    mma_scores<<<dim3(16, 16, NB), 256>>>(s1h, s1l, s2h, s2l, out);

    // exp + dustbin + transpose
    expk_kernel<<<dim3(65, 65, NB), dim3(32, 8)>>>(out, bin, Kh, KT);

    // Sinkhorn: persistent kernel, 100 iterations, internal grid barriers
    reset_bar<<<1, 1>>>();
    sink_persist<<<NBLK, 1024>>>(Kh, KT, a, bv);

    // out = exp(S) * a_i * b_j * (m+n)
    final_kernel<<<dim3(NP, NB), 256>>>(out, a, bv);
}